// round 14
// baseline (speedup 1.0000x reference)
#include <cuda_runtime.h>

// MMD_53008486367839 — batched persistence-diagram MMD with RBF kernel.
// B=64, N=M=1024, WIDTH=DECAY=1.
//
// Mercer feature expansion (validated R7+):
//   mmd_b = sum_{a+b<=20} c_ab F_ab^2,  c_ab = 2^(a+b)/(a! b!),
//   F_ab  = sum_i ps_i u_i^a v_i^b,  ps_i = s_i e^{-u^2-v^2},
//   s_i = +lifetime (X), -lifetime (Y).
//
// R14: point-pair-major power layout + packed f32x2 FMAs.
//   spu_t[ipair][row][par] (row stride 2, pair stride 52 words, 16B aligned):
//   one LDS.128 = 2 rows x 2 points. Lane = 4x4 (a,b) register tile over
//   {ta+tb<=5}; per point-pair: 4 LDS.128 + 16 packed FMAs (2 pts/instr).
//   Cross-warp reduce via stride-17 shared slab (conflict-free), per-batch
//   counters, final counter sums 64 batch values in fixed order.
// Single launch, zero-free, deterministic.

#define BATCH 64
#define NPTS  1024
#define D     20
#define NROW  24             // rows 0..23; 21..23 padding (masked by coeffs)
#define PSTR  52             // words per pair record (2*NROW + 4 pad; mult of 4)
#define NPAIR 128            // point pairs per 256-pt tile
#define CPB   8              // chunks (blocks) per batch
#define TILEPTS 256
#define GRID  (BATCH * CPB)  // 512
#define NSL   512            // 32 lanes * 16 slots per block
#define SSTR  17             // sacc lane stride (conflict-free)
#define UVWORDS (NPAIR * PSTR)        // 6656 words per array

__device__ float g_part[GRID][NSL];
__device__ float g_bval[BATCH];
__device__ int   g_bctr[BATCH];       // zero-init; reset after use
__device__ int   g_fctr;

__constant__ float c_inv_fact[NROW] = {
    1.0f, 1.0f, 0.5f, 1.6666666666666666e-01f, 4.1666666666666664e-02f,
    8.3333333333333332e-03f, 1.3888888888888889e-03f, 1.9841269841269841e-04f,
    2.4801587301587302e-05f, 2.7557319223985893e-06f, 2.7557319223985888e-07f,
    2.5052108385441720e-08f, 2.0876756987868100e-09f, 1.6059043836821613e-10f,
    1.1470745597729725e-11f, 7.6471637318198164e-13f, 4.7794773323873853e-14f,
    2.8114572543455206e-15f, 1.5619206968586226e-16f, 8.2206352466243295e-18f,
    4.1103176233121648e-19f, 0.0f, 0.0f, 0.0f};

// lane -> 4x4 tile origin (ta,tb): 21 tiles of {ta+tb<=5}; lanes 21..31 dup
// tile 0 (masked in the reduce).
__constant__ unsigned char c_ta[32] =
    {0,0,0,0,0,0, 1,1,1,1,1, 2,2,2,2, 3,3,3, 4,4, 5, 0,0,0,0,0,0,0,0,0,0,0};
__constant__ unsigned char c_tb[32] =
    {0,1,2,3,4,5, 0,1,2,3,4, 0,1,2,3, 0,1,2, 0,1, 0, 0,0,0,0,0,0,0,0,0,0,0};

typedef unsigned long long ull;

__device__ __forceinline__ ull fma2(ull a, ull b, ull c) {
    ull r; asm("fma.rn.f32x2 %0, %1, %2, %3;" : "=l"(r) : "l"(a), "l"(b), "l"(c));
    return r;
}
__device__ __forceinline__ float lo2(ull a) { return __uint_as_float((unsigned)a); }
__device__ __forceinline__ float hi2(ull a) { return __uint_as_float((unsigned)(a >> 32)); }
__device__ __forceinline__ float ex2f_(float x) {
    float y; asm("ex2.approx.ftz.f32 %0, %1;" : "=f"(y) : "f"(x)); return y;
}

__global__ void __launch_bounds__(256) mmd_fused(const float* __restrict__ X,
                                                 const float* __restrict__ Y,
                                                 const float* __restrict__ weights,
                                                 const float* __restrict__ num_samples,
                                                 float* __restrict__ out) {
    // spu_t | spv_t, each NPAIR*PSTR words; 53.2 KB total. Reused as sacc.
    __shared__ __align__(16) float smem[2 * UVWORDS];
    __shared__ float warp_sums[8];
    __shared__ int   s_rank;

    const int blk   = blockIdx.x;
    const int b     = blk >> 3;
    const int chunk = blk & 7;
    const int t     = threadIdx.x;
    const int lane  = t & 31, wid = t >> 5;

    float* spu = smem;            // [ipair*PSTR + row*2 + par] = ps * u^row
    float* spv = smem + UVWORDS;  // [ipair*PSTR + row*2 + par] = v^row

    // ---- phase 1: one point per thread -> pair-interleaved power rows ----
    {
        int p = chunk * TILEPTS + t;          // merged index 0..2047
        float2 xy; float sgn;
        if (p < NPTS) {
            xy = __ldg((const float2*)(X + ((size_t)b * NPTS + p) * 2));
            sgn = 1.0f;
        } else {
            xy = __ldg((const float2*)(Y + ((size_t)b * NPTS + (p - NPTS)) * 2));
            sgn = -1.0f;
        }
        const float LOG2E = 1.4426950408889634f;
        float u = xy.x, v = xy.y - xy.x;      // (birth, lifetime)
        float ps = sgn * v * ex2f_(-fmaf(u, u, v * v) * LOG2E);

        int base = (t >> 1) * PSTR + (t & 1); // my pair record, my parity slot
        float pw = ps;
        spu[base] = pw;
        #pragma unroll
        for (int a = 1; a < NROW; a++) { pw *= u; spu[base + 2 * a] = pw; }
        pw = 1.0f;
        spv[base] = 1.0f;
        #pragma unroll
        for (int bb = 1; bb < NROW; bb++) { pw *= v; spv[base + 2 * bb] = pw; }
    }
    __syncthreads();

    // ---- phase 2: packed 4x4 tile; warp owns 16 point-pairs ----
    ull acc[16];
    #pragma unroll
    for (int r = 0; r < 16; r++) acc[r] = 0ull;
    {
        const int ro = 8 * (int)c_ta[lane];   // word offset of my u rows
        const int co = 8 * (int)c_tb[lane];   // word offset of my v rows
        #pragma unroll 4
        for (int k = 0; k < NPAIR / 8; k++) {
            int ip = wid * (NPAIR / 8) + k;
            const float* pb = smem + ip * PSTR;
            // u rows 4ta..4ta+3, packed (par0,par1) per row
            ulonglong2 uq0 = *(const ulonglong2*)(pb + ro);
            ulonglong2 uq1 = *(const ulonglong2*)(pb + ro + 4);
            const float* qb = pb + UVWORDS;
            ulonglong2 vq0 = *(const ulonglong2*)(qb + co);
            ulonglong2 vq1 = *(const ulonglong2*)(qb + co + 4);
            ull ur[4] = {uq0.x, uq0.y, uq1.x, uq1.y};
            ull vr[4] = {vq0.x, vq0.y, vq1.x, vq1.y};
            #pragma unroll
            for (int r = 0; r < 4; r++)
                #pragma unroll
                for (int c = 0; c < 4; c++)
                    acc[r * 4 + c] = fma2(ur[r], vr[c], acc[r * 4 + c]);
        }
    }
    __syncthreads();   // power rows fully consumed; smem reusable

    // ---- cross-warp reduce via stride-17 shared slab, store partials ----
    {
        float* sacc = smem;                   // [8][32*SSTR]
        #pragma unroll
        for (int r = 0; r < 16; r++)
            sacc[wid * (32 * SSTR) + lane * SSTR + r] = lo2(acc[r]) + hi2(acc[r]);
        __syncthreads();
        float* gp = g_part[blk];
        #pragma unroll
        for (int s = t; s < NSL; s += 256) {
            int sl = (s >> 4) * SSTR + (s & 15);
            float v2 = 0.0f;
            #pragma unroll
            for (int w = 0; w < 8; w++) v2 += sacc[w * (32 * SSTR) + sl];
            gp[s] = v2;
        }
    }

    // ---- per-batch completion counter ----
    __threadfence();
    __syncthreads();
    if (t == 0) s_rank = atomicAdd(&g_bctr[b], 1);
    __syncthreads();
    if (s_rank != CPB - 1) return;

    // ======== batch reduce (last block of each batch; 64 in parallel) ======
    if (t == 0) g_bctr[b] = 0;                // reset for next replay
    __threadfence();

    float val = 0.0f;
    #pragma unroll
    for (int s = t; s < NSL; s += 256) {
        int ln = s >> 4, r = s & 15;
        int A  = 4 * (int)c_ta[ln] + (r >> 2);    // <= 23, in-bounds
        int Bc = 4 * (int)c_tb[ln] + (r & 3);
        float F = 0.0f;
        #pragma unroll
        for (int c2 = 0; c2 < CPB; c2++) F += g_part[(b << 3) | c2][s];
        bool valid = (ln < 21) && (A + Bc <= D);
        float coeff = valid ? exp2f((float)(A + Bc)) * c_inv_fact[A] * c_inv_fact[Bc]
                            : 0.0f;
        val = fmaf(coeff * F, F, val);
    }

    #pragma unroll
    for (int o = 16; o > 0; o >>= 1)
        val += __shfl_down_sync(0xFFFFFFFFu, val, o);
    if (lane == 0) warp_sums[wid] = val;
    __syncthreads();

    if (t == 0) {
        float bs = 0.0f;
        #pragma unroll
        for (int w = 0; w < 8; w++) bs += warp_sums[w];
        float n = __ldg(&num_samples[b]);
        g_bval[b] = bs * __ldg(&weights[b]) / (n * n);

        __threadfence();
        int rank = atomicAdd(&g_fctr, 1);
        if (rank == BATCH - 1) {
            __threadfence();
            float tot = 0.0f;
            #pragma unroll 8
            for (int i = 0; i < BATCH; i++) tot += g_bval[i];
            out[0] = tot;
            g_fctr = 0;                       // reset for next replay
        }
    }
}

// ---------------------------------------------------------------------------
extern "C" void kernel_launch(void* const* d_in, const int* in_sizes, int n_in,
                              void* d_out, int out_size) {
    const float* X  = (const float*)d_in[0];
    const float* Y  = (const float*)d_in[1];
    const float* w  = (const float*)d_in[2];
    const float* ns = (const float*)d_in[3];
    float* out = (float*)d_out;

    mmd_fused<<<GRID, 256>>>(X, Y, w, ns, out);
}

// round 15
// speedup vs baseline: 1.0186x; 1.0186x over previous
#include <cuda_runtime.h>

// MMD_53008486367839 — batched persistence-diagram MMD with RBF kernel.
// B=64, N=M=1024, WIDTH=DECAY=1.
//
// Mercer feature expansion (validated R7+):
//   mmd_b = sum_{a+b<=20} c_ab F_ab^2,  c_ab = 2^(a+b)/(a! b!),
//   F_ab  = sum_i ps_i u_i^a v_i^b,  ps_i = s_i e^{-u^2-v^2},
//   s_i = +lifetime (X), -lifetime (Y).
//
// R15 = R14 with ONE change: __threadfence() (gpu scope -> MEMBAR.GPU +
// CCTL.IVALL L1-flush) was executed by ALL 256 threads of every block.
// Now: __syncthreads() orders the CTA's partial stores, then THREAD 0 ALONE
// issues the release fence + counter atomic (cumulative release publishes
// the whole CTA's stores). Acquire fences remain only in the 64 tail blocks
// and the final thread. Fence executions drop 131K -> ~600.

#define BATCH 64
#define NPTS  1024
#define D     20
#define NROW  24             // rows 0..23; 21..23 padding (masked by coeffs)
#define PSTR  52             // words per pair record (2*NROW + 4 pad)
#define NPAIR 128            // point pairs per 256-pt tile
#define CPB   8              // chunks (blocks) per batch
#define TILEPTS 256
#define GRID  (BATCH * CPB)  // 512
#define NSL   512            // 32 lanes * 16 slots per block
#define SSTR  17             // sacc lane stride (conflict-free)
#define UVWORDS (NPAIR * PSTR)        // 6656 words per array

__device__ float g_part[GRID][NSL];
__device__ float g_bval[BATCH];
__device__ int   g_bctr[BATCH];       // zero-init; reset after use
__device__ int   g_fctr;

__constant__ float c_inv_fact[NROW] = {
    1.0f, 1.0f, 0.5f, 1.6666666666666666e-01f, 4.1666666666666664e-02f,
    8.3333333333333332e-03f, 1.3888888888888889e-03f, 1.9841269841269841e-04f,
    2.4801587301587302e-05f, 2.7557319223985893e-06f, 2.7557319223985888e-07f,
    2.5052108385441720e-08f, 2.0876756987868100e-09f, 1.6059043836821613e-10f,
    1.1470745597729725e-11f, 7.6471637318198164e-13f, 4.7794773323873853e-14f,
    2.8114572543455206e-15f, 1.5619206968586226e-16f, 8.2206352466243295e-18f,
    4.1103176233121648e-19f, 0.0f, 0.0f, 0.0f};

// lane -> 4x4 tile origin (ta,tb): 21 tiles of {ta+tb<=5}; lanes 21..31 dup
// tile 0 (masked in the reduce).
__constant__ unsigned char c_ta[32] =
    {0,0,0,0,0,0, 1,1,1,1,1, 2,2,2,2, 3,3,3, 4,4, 5, 0,0,0,0,0,0,0,0,0,0,0};
__constant__ unsigned char c_tb[32] =
    {0,1,2,3,4,5, 0,1,2,3,4, 0,1,2,3, 0,1,2, 0,1, 0, 0,0,0,0,0,0,0,0,0,0,0};

typedef unsigned long long ull;

__device__ __forceinline__ ull fma2(ull a, ull b, ull c) {
    ull r; asm("fma.rn.f32x2 %0, %1, %2, %3;" : "=l"(r) : "l"(a), "l"(b), "l"(c));
    return r;
}
__device__ __forceinline__ float lo2(ull a) { return __uint_as_float((unsigned)a); }
__device__ __forceinline__ float hi2(ull a) { return __uint_as_float((unsigned)(a >> 32)); }
__device__ __forceinline__ float ex2f_(float x) {
    float y; asm("ex2.approx.ftz.f32 %0, %1;" : "=f"(y) : "f"(x)); return y;
}

__global__ void __launch_bounds__(256) mmd_fused(const float* __restrict__ X,
                                                 const float* __restrict__ Y,
                                                 const float* __restrict__ weights,
                                                 const float* __restrict__ num_samples,
                                                 float* __restrict__ out) {
    // spu_t | spv_t, each NPAIR*PSTR words; 53.2 KB total. Reused as sacc.
    __shared__ __align__(16) float smem[2 * UVWORDS];
    __shared__ float warp_sums[8];
    __shared__ int   s_rank;

    const int blk   = blockIdx.x;
    const int b     = blk >> 3;
    const int chunk = blk & 7;
    const int t     = threadIdx.x;
    const int lane  = t & 31, wid = t >> 5;

    float* spu = smem;            // [ipair*PSTR + row*2 + par] = ps * u^row
    float* spv = smem + UVWORDS;  // [ipair*PSTR + row*2 + par] = v^row

    // ---- phase 1: one point per thread -> pair-interleaved power rows ----
    {
        int p = chunk * TILEPTS + t;          // merged index 0..2047
        float2 xy; float sgn;
        if (p < NPTS) {
            xy = __ldg((const float2*)(X + ((size_t)b * NPTS + p) * 2));
            sgn = 1.0f;
        } else {
            xy = __ldg((const float2*)(Y + ((size_t)b * NPTS + (p - NPTS)) * 2));
            sgn = -1.0f;
        }
        const float LOG2E = 1.4426950408889634f;
        float u = xy.x, v = xy.y - xy.x;      // (birth, lifetime)
        float ps = sgn * v * ex2f_(-fmaf(u, u, v * v) * LOG2E);

        int base = (t >> 1) * PSTR + (t & 1); // my pair record, my parity slot
        float pw = ps;
        spu[base] = pw;
        #pragma unroll
        for (int a = 1; a < NROW; a++) { pw *= u; spu[base + 2 * a] = pw; }
        pw = 1.0f;
        spv[base] = 1.0f;
        #pragma unroll
        for (int bb = 1; bb < NROW; bb++) { pw *= v; spv[base + 2 * bb] = pw; }
    }
    __syncthreads();

    // ---- phase 2: packed 4x4 tile; warp owns 16 point-pairs ----
    ull acc[16];
    #pragma unroll
    for (int r = 0; r < 16; r++) acc[r] = 0ull;
    {
        const int ro = 8 * (int)c_ta[lane];   // word offset of my u rows
        const int co = 8 * (int)c_tb[lane];   // word offset of my v rows
        #pragma unroll 4
        for (int k = 0; k < NPAIR / 8; k++) {
            int ip = wid * (NPAIR / 8) + k;
            const float* pb = smem + ip * PSTR;
            ulonglong2 uq0 = *(const ulonglong2*)(pb + ro);
            ulonglong2 uq1 = *(const ulonglong2*)(pb + ro + 4);
            const float* qb = pb + UVWORDS;
            ulonglong2 vq0 = *(const ulonglong2*)(qb + co);
            ulonglong2 vq1 = *(const ulonglong2*)(qb + co + 4);
            ull ur[4] = {uq0.x, uq0.y, uq1.x, uq1.y};
            ull vr[4] = {vq0.x, vq0.y, vq1.x, vq1.y};
            #pragma unroll
            for (int r = 0; r < 4; r++)
                #pragma unroll
                for (int c = 0; c < 4; c++)
                    acc[r * 4 + c] = fma2(ur[r], vr[c], acc[r * 4 + c]);
        }
    }
    __syncthreads();   // power rows fully consumed; smem reusable

    // ---- cross-warp reduce via stride-17 shared slab, store partials ----
    {
        float* sacc = smem;                   // [8][32*SSTR]
        #pragma unroll
        for (int r = 0; r < 16; r++)
            sacc[wid * (32 * SSTR) + lane * SSTR + r] = lo2(acc[r]) + hi2(acc[r]);
        __syncthreads();
        float* gp = g_part[blk];
        #pragma unroll
        for (int s = t; s < NSL; s += 256) {
            int sl = (s >> 4) * SSTR + (s & 15);
            float v2 = 0.0f;
            #pragma unroll
            for (int w = 0; w < 8; w++) v2 += sacc[w * (32 * SSTR) + sl];
            gp[s] = v2;
        }
    }

    // ---- per-batch completion counter: single-thread release fence ----
    __syncthreads();                          // CTA stores ordered before t0
    if (t == 0) {
        __threadfence();                      // cumulative release (1 thread)
        s_rank = atomicAdd(&g_bctr[b], 1);
    }
    __syncthreads();
    if (s_rank != CPB - 1) return;

    // ======== batch reduce (last block of each batch; 64 in parallel) ======
    if (t == 0) g_bctr[b] = 0;                // reset for next replay
    __threadfence();                          // acquire (tail blocks only)
    __syncthreads();

    float val = 0.0f;
    #pragma unroll
    for (int s = t; s < NSL; s += 256) {
        int ln = s >> 4, r = s & 15;
        int A  = 4 * (int)c_ta[ln] + (r >> 2);    // <= 23, in-bounds
        int Bc = 4 * (int)c_tb[ln] + (r & 3);
        float F = 0.0f;
        #pragma unroll
        for (int c2 = 0; c2 < CPB; c2++) F += g_part[(b << 3) | c2][s];
        bool valid = (ln < 21) && (A + Bc <= D);
        float coeff = valid ? exp2f((float)(A + Bc)) * c_inv_fact[A] * c_inv_fact[Bc]
                            : 0.0f;
        val = fmaf(coeff * F, F, val);
    }

    #pragma unroll
    for (int o = 16; o > 0; o >>= 1)
        val += __shfl_down_sync(0xFFFFFFFFu, val, o);
    if (lane == 0) warp_sums[wid] = val;
    __syncthreads();

    if (t == 0) {
        float bs = 0.0f;
        #pragma unroll
        for (int w = 0; w < 8; w++) bs += warp_sums[w];
        float n = __ldg(&num_samples[b]);
        g_bval[b] = bs * __ldg(&weights[b]) / (n * n);

        __threadfence();                      // release g_bval (1 thread)
        int rank = atomicAdd(&g_fctr, 1);
        if (rank == BATCH - 1) {
            __threadfence();                  // acquire (final thread only)
            float tot = 0.0f;
            #pragma unroll 8
            for (int i = 0; i < BATCH; i++) tot += g_bval[i];
            out[0] = tot;
            g_fctr = 0;                       // reset for next replay
        }
    }
}

// ---------------------------------------------------------------------------
extern "C" void kernel_launch(void* const* d_in, const int* in_sizes, int n_in,
                              void* d_out, int out_size) {
    const float* X  = (const float*)d_in[0];
    const float* Y  = (const float*)d_in[1];
    const float* w  = (const float*)d_in[2];
    const float* ns = (const float*)d_in[3];
    float* out = (float*)d_out;

    mmd_fused<<<GRID, 256>>>(X, Y, w, ns, out);
}

// round 17
// speedup vs baseline: 1.1442x; 1.1233x over previous
#include <cuda_runtime.h>

// MMD_53008486367839 — batched persistence-diagram MMD with RBF kernel.
// B=64, N=M=1024, WIDTH=DECAY=1.
//
// Mercer feature expansion (validated R7+):
//   mmd_b = sum_{a+b<=20} c_ab F_ab^2,  c_ab = 2^(a+b)/(a! b!),
//   F_ab  = sum_i ps_i u_i^a v_i^b,  ps_i = s_i e^{-u^2-v^2},
//   s_i = +lifetime (X), -lifetime (Y).
//
// R16: occupancy + overlap restructure.
//  - 1024 blocks x 128 threads (128-pt tiles): ~7 blocks/SM (reg- and
//    smem-feasible 8), double the block parallelism of R15.
//  - per-block feature partials accumulated by float atomicAdd into
//    g_F[batch][slot] DURING production (overlapped, no post-hoc gather).
//  - per-batch counter: 16th block applies coeffs to 512 floats, resets
//    g_F[b] for the next graph replay (zero-free); final counter block's
//    warp 0 sums 64 batch values in fixed shuffle order.
// Single launch, deterministic up to float-atomic rounding (validated
// acceptable in R3-R8).

#define BATCH 64
#define NPTS  1024
#define D     20
#define NROW  24             // rows 0..23; 21..23 padding (masked by coeffs)
#define PSTR  52             // words per pair record (2*NROW + 4 pad)
#define TILEPTS 128
#define NPAIR 64             // point pairs per tile
#define CPB   16             // chunks (blocks) per batch
#define TPB   128            // 4 warps
#define GRID  (BATCH * CPB)  // 1024
#define NSL   512            // 32 lanes * 16 slots
#define SSTR  17             // sacc lane stride (conflict-free)
#define UVWORDS (NPAIR * PSTR)   // 3328 words per array

__device__ float g_F[BATCH][NSL];     // atomic feature accumulators (zero-init;
                                      // reset by each batch's tail block)
__device__ float g_bval[BATCH];
__device__ int   g_bctr[BATCH];       // zero-init; reset after use
__device__ int   g_fctr;

__constant__ float c_inv_fact[NROW] = {
    1.0f, 1.0f, 0.5f, 1.6666666666666666e-01f, 4.1666666666666664e-02f,
    8.3333333333333332e-03f, 1.3888888888888889e-03f, 1.9841269841269841e-04f,
    2.4801587301587302e-05f, 2.7557319223985893e-06f, 2.7557319223985888e-07f,
    2.5052108385441720e-08f, 2.0876756987868100e-09f, 1.6059043836821613e-10f,
    1.1470745597729725e-11f, 7.6471637318198164e-13f, 4.7794773323873853e-14f,
    2.8114572543455206e-15f, 1.5619206968586226e-16f, 8.2206352466243295e-18f,
    4.1103176233121648e-19f, 0.0f, 0.0f, 0.0f};

// lane -> 4x4 tile origin (ta,tb): 21 tiles of {ta+tb<=5}; lanes 21..31 dup
// tile 0 (masked in the reduce).
__constant__ unsigned char c_ta[32] =
    {0,0,0,0,0,0, 1,1,1,1,1, 2,2,2,2, 3,3,3, 4,4, 5, 0,0,0,0,0,0,0,0,0,0,0};
__constant__ unsigned char c_tb[32] =
    {0,1,2,3,4,5, 0,1,2,3,4, 0,1,2,3, 0,1,2, 0,1, 0, 0,0,0,0,0,0,0,0,0,0,0};

typedef unsigned long long ull;

__device__ __forceinline__ ull fma2(ull a, ull b, ull c) {
    ull r; asm("fma.rn.f32x2 %0, %1, %2, %3;" : "=l"(r) : "l"(a), "l"(b), "l"(c));
    return r;
}
__device__ __forceinline__ float lo2(ull a) { return __uint_as_float((unsigned)a); }
__device__ __forceinline__ float hi2(ull a) { return __uint_as_float((unsigned)(a >> 32)); }
__device__ __forceinline__ float ex2f_(float x) {
    float y; asm("ex2.approx.ftz.f32 %0, %1;" : "=f"(y) : "f"(x)); return y;
}

__global__ void __launch_bounds__(TPB) mmd_fused(const float* __restrict__ X,
                                                 const float* __restrict__ Y,
                                                 const float* __restrict__ weights,
                                                 const float* __restrict__ num_samples,
                                                 float* __restrict__ out) {
    // spu_t | spv_t pair-interleaved records; 26.6 KB. Reused as sacc slab.
    __shared__ __align__(16) float smem[2 * UVWORDS];
    __shared__ float warp_sums[4];
    __shared__ int   s_rank;
    __shared__ int   s_final;

    const int blk   = blockIdx.x;
    const int b     = blk >> 4;           // / CPB
    const int chunk = blk & (CPB - 1);
    const int t     = threadIdx.x;
    const int lane  = t & 31, wid = t >> 5;

    float* spu = smem;            // [ipair*PSTR + row*2 + par] = ps * u^row
    float* spv = smem + UVWORDS;  // [ipair*PSTR + row*2 + par] = v^row

    // ---- phase 1: one point per thread -> pair-interleaved power rows ----
    {
        int p = chunk * TILEPTS + t;      // merged index 0..2047
        float2 xy; float sgn;
        if (p < NPTS) {
            xy = __ldg((const float2*)(X + ((size_t)b * NPTS + p) * 2));
            sgn = 1.0f;
        } else {
            xy = __ldg((const float2*)(Y + ((size_t)b * NPTS + (p - NPTS)) * 2));
            sgn = -1.0f;
        }
        const float LOG2E = 1.4426950408889634f;
        float u = xy.x, v = xy.y - xy.x;  // (birth, lifetime)
        float ps = sgn * v * ex2f_(-fmaf(u, u, v * v) * LOG2E);

        int base = (t >> 1) * PSTR + (t & 1);
        float pw = ps;
        spu[base] = pw;
        #pragma unroll
        for (int a = 1; a < NROW; a++) { pw *= u; spu[base + 2 * a] = pw; }
        pw = 1.0f;
        spv[base] = 1.0f;
        #pragma unroll
        for (int bb = 1; bb < NROW; bb++) { pw *= v; spv[base + 2 * bb] = pw; }
    }
    __syncthreads();

    // ---- phase 2: packed 4x4 tile; warp owns 16 point-pairs ----
    ull acc[16];
    #pragma unroll
    for (int r = 0; r < 16; r++) acc[r] = 0ull;
    {
        const int ro = 8 * (int)c_ta[lane];   // word offset of my u rows
        const int co = 8 * (int)c_tb[lane];   // word offset of my v rows
        #pragma unroll 4
        for (int k = 0; k < 16; k++) {
            int ip = wid * 16 + k;
            const float* pb = smem + ip * PSTR;
            ulonglong2 uq0 = *(const ulonglong2*)(pb + ro);
            ulonglong2 uq1 = *(const ulonglong2*)(pb + ro + 4);
            const float* qb = pb + UVWORDS;
            ulonglong2 vq0 = *(const ulonglong2*)(qb + co);
            ulonglong2 vq1 = *(const ulonglong2*)(qb + co + 4);
            ull ur[4] = {uq0.x, uq0.y, uq1.x, uq1.y};
            ull vr[4] = {vq0.x, vq0.y, vq1.x, vq1.y};
            #pragma unroll
            for (int r = 0; r < 4; r++)
                #pragma unroll
                for (int c = 0; c < 4; c++)
                    acc[r * 4 + c] = fma2(ur[r], vr[c], acc[r * 4 + c]);
        }
    }
    __syncthreads();   // power rows fully consumed; smem reusable

    // ---- cross-warp reduce (stride-17 slab) + overlapped atomic publish ----
    {
        float* sacc = smem;                   // [4][32*SSTR]
        #pragma unroll
        for (int r = 0; r < 16; r++)
            sacc[wid * (32 * SSTR) + lane * SSTR + r] = lo2(acc[r]) + hi2(acc[r]);
        __syncthreads();
        #pragma unroll
        for (int s = t; s < NSL; s += TPB) {
            int sl = (s >> 4) * SSTR + (s & 15);
            float v2 = 0.0f;
            #pragma unroll
            for (int w = 0; w < 4; w++) v2 += sacc[w * (32 * SSTR) + sl];
            atomicAdd(&g_F[b][s], v2);        // overlapped with other blocks
        }
    }

    // ---- per-batch completion counter (atomics are device-coherent) ----
    __syncthreads();
    if (t == 0) s_rank = atomicAdd(&g_bctr[b], 1);
    __syncthreads();
    if (s_rank != CPB - 1) return;

    // ======== batch tail (last block of each batch; 64 run in parallel) ====
    if (t == 0) g_bctr[b] = 0;                // reset for next replay
    __threadfence();                          // acquire prior atomics

    float val = 0.0f;
    #pragma unroll
    for (int s = t; s < NSL; s += TPB) {
        int ln = s >> 4, r = s & 15;
        int A  = 4 * (int)c_ta[ln] + (r >> 2);    // <= 23, in-bounds
        int Bc = 4 * (int)c_tb[ln] + (r & 3);
        float F = __ldcg(&g_F[b][s]);
        g_F[b][s] = 0.0f;                     // reset for next replay
        bool valid = (ln < 21) && (A + Bc <= D);
        float coeff = valid ? exp2f((float)(A + Bc)) * c_inv_fact[A] * c_inv_fact[Bc]
                            : 0.0f;
        val = fmaf(coeff * F, F, val);
    }

    #pragma unroll
    for (int o = 16; o > 0; o >>= 1)
        val += __shfl_down_sync(0xFFFFFFFFu, val, o);
    if (lane == 0) warp_sums[wid] = val;
    __syncthreads();

    if (t == 0) {
        float bs = warp_sums[0] + warp_sums[1] + warp_sums[2] + warp_sums[3];
        float n  = __ldg(&num_samples[b]);
        g_bval[b] = bs * __ldg(&weights[b]) / (n * n);
        __threadfence();                      // release g_bval
        int rank = atomicAdd(&g_fctr, 1);
        s_final = (rank == BATCH - 1);
    }
    __syncthreads();
    if (!s_final) return;

    // ======== final: warp 0 of the very last tail block sums 64 values ====
    if (wid == 0) {
        __threadfence();                      // acquire all g_bval
        float v0 = __ldcg(&g_bval[lane]);
        float v1 = __ldcg(&g_bval[lane + 32]);
        float vsum = v0 + v1;
        #pragma unroll
        for (int o = 16; o > 0; o >>= 1)
            vsum += __shfl_down_sync(0xFFFFFFFFu, vsum, o);
        if (lane == 0) {
            out[0] = vsum;
            g_fctr = 0;                       // reset for next replay
        }
    }
}

// ---------------------------------------------------------------------------
extern "C" void kernel_launch(void* const* d_in, const int* in_sizes, int n_in,
                              void* d_out, int out_size) {
    const float* X  = (const float*)d_in[0];
    const float* Y  = (const float*)d_in[1];
    const float* w  = (const float*)d_in[2];
    const float* ns = (const float*)d_in[3];
    float* out = (float*)d_out;

    mmd_fused<<<GRID, TPB>>>(X, Y, w, ns, out);
}